// round 14
// baseline (speedup 1.0000x reference)
#include <cuda_runtime.h>
#include <cuda_fp16.h>
#include <cuda.h>
#include <cstdint>
#include <cstddef>

// Problem dims (fixed)
#define M_TOTAL 16384
#define N_TOTAL 16384
#define K_TOTAL 4096

// Tiling: BM=128, BN=256, BK=128 per stage (two 64-wide sub-blocks)
#define BM 128
#define BN 256
#define BKH 64                        // sub-block K width (128 B rows, SW128)
#define STAGES 2
#define NKITER (K_TOTAL / 128)        // 32 big iterations
#define A_SUB (BM * BKH * 2)          // 16384
#define B_SUB (BN * BKH * 2)          // 32768
#define A_PART (2 * A_SUB)            // 32768
#define STAGE_BYTES (A_PART + 2 * B_SUB)   // 98304
#define SMEM_HDR 1024
#define SMEM_TOTAL (1024 + SMEM_HDR + STAGES * STAGE_BYTES)  // 198656
#define GROUP_M 8
#define NUM_N (N_TOTAL / BN)          // 64
#define NTILES ((M_TOTAL / BM) * NUM_N)  // 8192

#define FULL_OFF(s)  ((s) * 16)
#define EMPTY_OFF(s) ((s) * 16 + 8)

// ---------------- fp16 scratch ----------------
__device__ __align__(1024) __half g_A[(size_t)M_TOTAL * K_TOTAL];  // 128 MB
__device__ __align__(1024) __half g_B[(size_t)N_TOTAL * K_TOTAL];  // 128 MB

// ---------------- device helpers ----------------
__device__ __forceinline__ uint32_t smem_u32(const void* p) {
    uint32_t a;
    asm("{ .reg .u64 t; cvta.to.shared.u64 t, %1; cvt.u32.u64 %0, t; }"
        : "=r"(a) : "l"(p));
    return a;
}

__device__ __forceinline__ void mbar_init(uint32_t mbar, uint32_t count) {
    asm volatile("mbarrier.init.shared.b64 [%0], %1;" :: "r"(mbar), "r"(count) : "memory");
}

__device__ __forceinline__ void mbar_expect_tx(uint32_t mbar, uint32_t bytes) {
    asm volatile("mbarrier.arrive.expect_tx.shared.b64 _, [%0], %1;"
                 :: "r"(mbar), "r"(bytes) : "memory");
}

__device__ __forceinline__ void mbar_arrive(uint32_t mbar) {
    asm volatile("mbarrier.arrive.shared.b64 _, [%0];" :: "r"(mbar) : "memory");
}

__device__ __forceinline__ void mbar_wait(uint32_t mbar, uint32_t parity) {
    asm volatile(
        "{\n\t.reg .pred P;\n\t"
        "LAB_WAIT_%=:\n\t"
        "mbarrier.try_wait.parity.acquire.cta.shared::cta.b64 P, [%0], %1, 0x989680;\n\t"
        "@P bra.uni LAB_DONE_%=;\n\t"
        "bra.uni LAB_WAIT_%=;\n\t"
        "LAB_DONE_%=:\n\t}"
        :: "r"(mbar), "r"(parity) : "memory");
}

__device__ __forceinline__ void tma_load_2d(uint32_t dst, const CUtensorMap* map,
                                            int x, int y, uint32_t mbar) {
    asm volatile(
        "cp.async.bulk.tensor.2d.shared::cta.global.tile.mbarrier::complete_tx::bytes "
        "[%0], [%1, {%2, %3}], [%4];"
        :: "r"(dst), "l"(map), "r"(x), "r"(y), "r"(mbar) : "memory");
}

#define LDSM4(R, ADDR) \
    asm volatile("ldmatrix.sync.aligned.m8n8.x4.shared.b16 {%0,%1,%2,%3}, [%4];" \
                 : "=r"((R)[0]), "=r"((R)[1]), "=r"((R)[2]), "=r"((R)[3]) \
                 : "r"(ADDR))

__device__ __forceinline__ void mma16816(float* c, const uint32_t* a,
                                         uint32_t b0, uint32_t b1) {
    asm volatile(
        "mma.sync.aligned.m16n8k16.row.col.f32.f16.f16.f32 "
        "{%0,%1,%2,%3}, {%4,%5,%6,%7}, {%8,%9}, {%0,%1,%2,%3};"
        : "+f"(c[0]), "+f"(c[1]), "+f"(c[2]), "+f"(c[3])
        : "r"(a[0]), "r"(a[1]), "r"(a[2]), "r"(a[3]), "r"(b0), "r"(b1));
}

// tile id -> (m0, n0) grouped raster
__device__ __forceinline__ void tile_coords(int tile_id, int& m0, int& n0) {
    const int per_group = GROUP_M * NUM_N;
    int g = tile_id / per_group;
    int r = tile_id - g * per_group;
    m0 = (g * GROUP_M + (r % GROUP_M)) * BM;
    n0 = (r / GROUP_M) * BN;
}

// ---------------- fused conversion kernel ----------------
__global__ void cvt_fused_kernel(const float4* __restrict__ x,
                                 const int4* __restrict__ q,
                                 uint4* __restrict__ dstA,
                                 uint4* __restrict__ dstB,
                                 const float* __restrict__ scale_p,
                                 const float* __restrict__ zp_p, int n8) {
    const float s = __ldg(scale_p);
    const float z = __ldg(zp_p);
    int i = blockIdx.x * blockDim.x + threadIdx.x;
    int stride = gridDim.x * blockDim.x;
    for (; i < n8; i += stride) {
        float4 v0 = x[2 * i];
        float4 v1 = x[2 * i + 1];
        __half2 h0 = __floats2half2_rn(v0.x, v0.y);
        __half2 h1 = __floats2half2_rn(v0.z, v0.w);
        __half2 h2 = __floats2half2_rn(v1.x, v1.y);
        __half2 h3 = __floats2half2_rn(v1.z, v1.w);
        uint4 oa;
        oa.x = *reinterpret_cast<uint32_t*>(&h0);
        oa.y = *reinterpret_cast<uint32_t*>(&h1);
        oa.z = *reinterpret_cast<uint32_t*>(&h2);
        oa.w = *reinterpret_cast<uint32_t*>(&h3);
        dstA[i] = oa;
        int4 w0 = q[2 * i];
        int4 w1 = q[2 * i + 1];
        __half2 g0 = __floats2half2_rn(s * ((float)w0.x - z), s * ((float)w0.y - z));
        __half2 g1 = __floats2half2_rn(s * ((float)w0.z - z), s * ((float)w0.w - z));
        __half2 g2 = __floats2half2_rn(s * ((float)w1.x - z), s * ((float)w1.y - z));
        __half2 g3 = __floats2half2_rn(s * ((float)w1.z - z), s * ((float)w1.w - z));
        uint4 ob;
        ob.x = *reinterpret_cast<uint32_t*>(&g0);
        ob.y = *reinterpret_cast<uint32_t*>(&g1);
        ob.z = *reinterpret_cast<uint32_t*>(&g2);
        ob.w = *reinterpret_cast<uint32_t*>(&g3);
        dstB[i] = ob;
    }
}

// ---------------- persistent GEMM kernel ----------------
__global__ void __launch_bounds__(256, 1)
gemm_hmma_kernel(const __grid_constant__ CUtensorMap tmA,
                 const __grid_constant__ CUtensorMap tmB,
                 const float* __restrict__ bias,
                 float* __restrict__ out) {
    extern __shared__ char smraw[];
    const uint32_t sb = (smem_u32(smraw) + 1023u) & ~1023u;
    const uint32_t data = sb + SMEM_HDR;

    const int tid = threadIdx.x;
    const int wid = tid >> 5;
    const int lane = tid & 31;
    const int warp_m = wid & 1;       // 2 warps over M (64 rows)
    const int warp_n = wid >> 1;      // 4 warps over N (64 cols)
    const int hsw = wid >> 2;         // warps 4-7 traverse sub-blocks in reverse

    const int bid = blockIdx.x;
    const int G = gridDim.x;
    const int ntiles_cta = (NTILES - 1 - bid) / G + 1;
    const int GI = ntiles_cta * NKITER;

    if (tid == 0) {
        #pragma unroll
        for (int s = 0; s < STAGES; ++s) {
            mbar_init(sb + FULL_OFF(s), 1);
            mbar_init(sb + EMPTY_OFF(s), 8);   // one arrive per warp
        }
    }
    __syncthreads();

    // prologue: fill both stages (tile 0, big-k = 0..1)
    if (tid == 0) {
        int m0p, n0p;
        tile_coords(bid, m0p, n0p);
        #pragma unroll
        for (int s = 0; s < STAGES; ++s) {
            uint32_t st = data + s * STAGE_BYTES;
            mbar_expect_tx(sb + FULL_OFF(s), STAGE_BYTES);
            tma_load_2d(st,                     &tmA, s * 128,      m0p, sb + FULL_OFF(s));
            tma_load_2d(st + A_SUB,             &tmA, s * 128 + 64, m0p, sb + FULL_OFF(s));
            tma_load_2d(st + A_PART,            &tmB, s * 128,      n0p, sb + FULL_OFF(s));
            tma_load_2d(st + A_PART + B_SUB,    &tmB, s * 128 + 64, n0p, sb + FULL_OFF(s));
        }
    }

    // per-thread ldmatrix offsets (relative to sub-block base)
    const int row16 = lane & 15;
    const uint32_t chalf = (lane >> 4) & 1;
    uint32_t a_off[4], b_off[4], a_xor[4], b_xor[4];
    #pragma unroll
    for (int t = 0; t < 4; ++t) {
        int ar = warp_m * 64 + t * 16 + row16;
        a_off[t] = (uint32_t)ar * 128u;
        a_xor[t] = (uint32_t)(ar & 7);
        int br = warp_n * 64 + t * 16 + row16;
        b_off[t] = (uint32_t)br * 128u;
        b_xor[t] = (uint32_t)(br & 7);
    }

    const int lm = lane >> 2;
    const int lc = (lane & 3) * 2;

    for (int tseq = 0; tseq < ntiles_cta; ++tseq) {
        const int tile_id = bid + tseq * G;
        int m0, n0;
        tile_coords(tile_id, m0, n0);

        float acc[4][8][4];
        #pragma unroll
        for (int mt = 0; mt < 4; ++mt)
            #pragma unroll
            for (int nt = 0; nt < 8; ++nt)
                #pragma unroll
                for (int i = 0; i < 4; ++i) acc[mt][nt][i] = 0.0f;

        for (int k = 0; k < NKITER; ++k) {
            const int gi = tseq * NKITER + k;
            const int s = gi & 1;
            const uint32_t ph = (uint32_t)((gi >> 1) & 1);
            const uint32_t stage = data + s * STAGE_BYTES;

            mbar_wait(sb + FULL_OFF(s), ph);

            // two sub-blocks; warps 4-7 take them in reverse order (h ^ hsw)
            // to decorrelate LDSM->MMA stalls between warps sharing an SMSP.
            #pragma unroll
            for (int h = 0; h < 2; ++h) {
                const uint32_t hh = (uint32_t)(h ^ hsw);
                const uint32_t baseA = stage + hh * A_SUB;
                const uint32_t baseB = stage + A_PART + hh * B_SUB;
                #pragma unroll
                for (int ks = 0; ks < 4; ++ks) {
                    uint32_t a[4][4], b[4][4];
                    const uint32_t chunk = ((uint32_t)ks << 1) | chalf;
                    #pragma unroll
                    for (int mt = 0; mt < 4; ++mt)
                        LDSM4(a[mt], baseA + a_off[mt] + ((chunk ^ a_xor[mt]) << 4));
                    #pragma unroll
                    for (int p = 0; p < 4; ++p)
                        LDSM4(b[p], baseB + b_off[p] + ((chunk ^ b_xor[p]) << 4));
                    #pragma unroll
                    for (int mt = 0; mt < 4; ++mt) {
                        #pragma unroll
                        for (int p = 0; p < 4; ++p) {
                            mma16816(acc[mt][2 * p],     a[mt], b[p][0], b[p][2]);
                            mma16816(acc[mt][2 * p + 1], a[mt], b[p][1], b[p][3]);
                        }
                    }
                }
            }

            if (lane == 0) mbar_arrive(sb + EMPTY_OFF(s));

            // producer: refill this stage with big-iter gi+2 (may cross tiles)
            if (tid == 0 && gi + STAGES < GI) {
                mbar_wait(sb + EMPTY_OFF(s), ph);
                const int gnext = gi + STAGES;
                const int ts2 = gnext >> 5;           // NKITER = 32
                const int k2 = gnext & 31;
                int m0p, n0p;
                tile_coords(bid + ts2 * G, m0p, n0p);
                mbar_expect_tx(sb + FULL_OFF(s), STAGE_BYTES);
                tma_load_2d(stage,                  &tmA, k2 * 128,      m0p, sb + FULL_OFF(s));
                tma_load_2d(stage + A_SUB,          &tmA, k2 * 128 + 64, m0p, sb + FULL_OFF(s));
                tma_load_2d(stage + A_PART,         &tmB, k2 * 128,      n0p, sb + FULL_OFF(s));
                tma_load_2d(stage + A_PART + B_SUB, &tmB, k2 * 128 + 64, n0p, sb + FULL_OFF(s));
            }
        }

        // ---------------- epilogue ----------------
        const int col0 = n0 + warp_n * 64 + lc;
        float2 bv[8];
        #pragma unroll
        for (int nt = 0; nt < 8; ++nt)
            bv[nt] = *reinterpret_cast<const float2*>(bias + col0 + nt * 8);

        #pragma unroll
        for (int mt = 0; mt < 4; ++mt) {
            const int r0 = m0 + warp_m * 64 + mt * 16 + lm;
            float* p0 = out + (size_t)r0 * N_TOTAL + col0;
            float* p1 = p0 + (size_t)8 * N_TOTAL;
            #pragma unroll
            for (int nt = 0; nt < 8; ++nt) {
                float2 v0 = {acc[mt][nt][0] + bv[nt].x, acc[mt][nt][1] + bv[nt].y};
                float2 v1 = {acc[mt][nt][2] + bv[nt].x, acc[mt][nt][3] + bv[nt].y};
                *reinterpret_cast<float2*>(p0 + nt * 8) = v0;
                *reinterpret_cast<float2*>(p1 + nt * 8) = v1;
            }
        }
    }
}

// ---------------- host ----------------
typedef CUresult (*PFN_encodeTiled)(CUtensorMap*, CUtensorMapDataType, cuuint32_t, void*,
                                    const cuuint64_t*, const cuuint64_t*,
                                    const cuuint32_t*, const cuuint32_t*,
                                    CUtensorMapInterleave, CUtensorMapSwizzle,
                                    CUtensorMapL2promotion, CUtensorMapFloatOOBfill);

static PFN_encodeTiled get_encode_fn() {
    void* p = nullptr;
    cudaDriverEntryPointQueryResult qr;
    cudaGetDriverEntryPointByVersion("cuTensorMapEncodeTiled", &p, 12000,
                                     cudaEnableDefault, &qr);
    return (PFN_encodeTiled)p;
}

static void make_tmap(PFN_encodeTiled enc, CUtensorMap* tm, void* base,
                      uint64_t rows, uint32_t box_rows) {
    cuuint64_t dims[2]    = {(cuuint64_t)K_TOTAL, (cuuint64_t)rows};
    cuuint64_t strides[1] = {(cuuint64_t)K_TOTAL * 2};
    cuuint32_t box[2]     = {(cuuint32_t)BKH, (cuuint32_t)box_rows};
    cuuint32_t es[2]      = {1, 1};
    enc(tm, CU_TENSOR_MAP_DATA_TYPE_FLOAT16, 2, base, dims, strides, box, es,
        CU_TENSOR_MAP_INTERLEAVE_NONE, CU_TENSOR_MAP_SWIZZLE_128B,
        CU_TENSOR_MAP_L2_PROMOTION_L2_128B, CU_TENSOR_MAP_FLOAT_OOB_FILL_NONE);
}

extern "C" void kernel_launch(void* const* d_in, const int* in_sizes, int n_in,
                              void* d_out, int out_size) {
    const float* x    = (const float*)d_in[0];
    const int*   qw   = (const int*)d_in[1];
    const float* sc   = (const float*)d_in[2];
    const float* zp   = (const float*)d_in[3];
    const float* bias = (const float*)d_in[4];
    float* out = (float*)d_out;

    void *pa = nullptr, *pb = nullptr;
    cudaGetSymbolAddress(&pa, g_A);
    cudaGetSymbolAddress(&pb, g_B);

    const int n8 = (int)(((size_t)M_TOTAL * K_TOTAL) / 8);
    cvt_fused_kernel<<<2048, 256>>>((const float4*)x, (const int4*)qw,
                                    (uint4*)pa, (uint4*)pb, sc, zp, n8);

    PFN_encodeTiled enc = get_encode_fn();
    CUtensorMap tmA, tmB;
    make_tmap(enc, &tmA, pa, M_TOTAL, BM);
    make_tmap(enc, &tmB, pb, N_TOTAL, BN);

    int sm_count = 148;
    cudaDeviceGetAttribute(&sm_count, cudaDevAttrMultiProcessorCount, 0);
    if (sm_count > NTILES) sm_count = NTILES;

    cudaFuncSetAttribute(gemm_hmma_kernel,
                         cudaFuncAttributeMaxDynamicSharedMemorySize, SMEM_TOTAL);
    gemm_hmma_kernel<<<sm_count, 256, SMEM_TOTAL>>>(tmA, tmB, bias, out);
}

// round 15
// speedup vs baseline: 1.0015x; 1.0015x over previous
#include <cuda_runtime.h>
#include <cuda_fp16.h>
#include <cuda.h>
#include <cstdint>
#include <cstddef>

// Problem dims (fixed)
#define M_TOTAL 16384
#define N_TOTAL 16384
#define K_TOTAL 4096

// Tiling: BM=128, BN=256, BK=128 per stage (two 64-wide sub-blocks)
#define BM 128
#define BN 256
#define BKH 64                        // sub-block K width (128 B rows, SW128)
#define STAGES 2
#define NKITER (K_TOTAL / 128)        // 32 big iterations
#define A_SUB (BM * BKH * 2)          // 16384
#define B_SUB (BN * BKH * 2)          // 32768
#define A_PART (2 * A_SUB)            // 32768
#define STAGE_BYTES (A_PART + 2 * B_SUB)   // 98304
#define SMEM_HDR 1024
#define SMEM_TOTAL (1024 + SMEM_HDR + STAGES * STAGE_BYTES)  // 198656
#define GROUP_M 8
#define NUM_N (N_TOTAL / BN)          // 64
#define NTILES ((M_TOTAL / BM) * NUM_N)  // 8192

#define FULL_OFF(s)  ((s) * 16)
#define EMPTY_OFF(s) ((s) * 16 + 8)

// ---------------- fp16 scratch ----------------
__device__ __align__(1024) __half g_A[(size_t)M_TOTAL * K_TOTAL];  // 128 MB
__device__ __align__(1024) __half g_B[(size_t)N_TOTAL * K_TOTAL];  // 128 MB

// ---------------- device helpers ----------------
__device__ __forceinline__ uint32_t smem_u32(const void* p) {
    uint32_t a;
    asm("{ .reg .u64 t; cvta.to.shared.u64 t, %1; cvt.u32.u64 %0, t; }"
        : "=r"(a) : "l"(p));
    return a;
}

__device__ __forceinline__ void mbar_init(uint32_t mbar, uint32_t count) {
    asm volatile("mbarrier.init.shared.b64 [%0], %1;" :: "r"(mbar), "r"(count) : "memory");
}

__device__ __forceinline__ void mbar_expect_tx(uint32_t mbar, uint32_t bytes) {
    asm volatile("mbarrier.arrive.expect_tx.shared.b64 _, [%0], %1;"
                 :: "r"(mbar), "r"(bytes) : "memory");
}

__device__ __forceinline__ void mbar_arrive(uint32_t mbar) {
    asm volatile("mbarrier.arrive.shared.b64 _, [%0];" :: "r"(mbar) : "memory");
}

__device__ __forceinline__ void mbar_wait(uint32_t mbar, uint32_t parity) {
    asm volatile(
        "{\n\t.reg .pred P;\n\t"
        "LAB_WAIT_%=:\n\t"
        "mbarrier.try_wait.parity.acquire.cta.shared::cta.b64 P, [%0], %1, 0x989680;\n\t"
        "@P bra.uni LAB_DONE_%=;\n\t"
        "bra.uni LAB_WAIT_%=;\n\t"
        "LAB_DONE_%=:\n\t}"
        :: "r"(mbar), "r"(parity) : "memory");
}

__device__ __forceinline__ void tma_load_2d(uint32_t dst, const CUtensorMap* map,
                                            int x, int y, uint32_t mbar) {
    asm volatile(
        "cp.async.bulk.tensor.2d.shared::cta.global.tile.mbarrier::complete_tx::bytes "
        "[%0], [%1, {%2, %3}], [%4];"
        :: "r"(dst), "l"(map), "r"(x), "r"(y), "r"(mbar) : "memory");
}

#define LDSM4(R, ADDR) \
    asm volatile("ldmatrix.sync.aligned.m8n8.x4.shared.b16 {%0,%1,%2,%3}, [%4];" \
                 : "=r"((R)[0]), "=r"((R)[1]), "=r"((R)[2]), "=r"((R)[3]) \
                 : "r"(ADDR))

__device__ __forceinline__ void mma16816(float* c, const uint32_t* a,
                                         uint32_t b0, uint32_t b1) {
    asm volatile(
        "mma.sync.aligned.m16n8k16.row.col.f32.f16.f16.f32 "
        "{%0,%1,%2,%3}, {%4,%5,%6,%7}, {%8,%9}, {%0,%1,%2,%3};"
        : "+f"(c[0]), "+f"(c[1]), "+f"(c[2]), "+f"(c[3])
        : "r"(a[0]), "r"(a[1]), "r"(a[2]), "r"(a[3]), "r"(b0), "r"(b1));
}

// tile id -> (m0, n0) grouped raster
__device__ __forceinline__ void tile_coords(int tile_id, int& m0, int& n0) {
    const int per_group = GROUP_M * NUM_N;
    int g = tile_id / per_group;
    int r = tile_id - g * per_group;
    m0 = (g * GROUP_M + (r % GROUP_M)) * BM;
    n0 = (r / GROUP_M) * BN;
}

// ---------------- fused conversion kernel ----------------
__global__ void cvt_fused_kernel(const float4* __restrict__ x,
                                 const int4* __restrict__ q,
                                 uint4* __restrict__ dstA,
                                 uint4* __restrict__ dstB,
                                 const float* __restrict__ scale_p,
                                 const float* __restrict__ zp_p, int n8) {
    const float s = __ldg(scale_p);
    const float z = __ldg(zp_p);
    int i = blockIdx.x * blockDim.x + threadIdx.x;
    int stride = gridDim.x * blockDim.x;
    for (; i < n8; i += stride) {
        float4 v0 = x[2 * i];
        float4 v1 = x[2 * i + 1];
        __half2 h0 = __floats2half2_rn(v0.x, v0.y);
        __half2 h1 = __floats2half2_rn(v0.z, v0.w);
        __half2 h2 = __floats2half2_rn(v1.x, v1.y);
        __half2 h3 = __floats2half2_rn(v1.z, v1.w);
        uint4 oa;
        oa.x = *reinterpret_cast<uint32_t*>(&h0);
        oa.y = *reinterpret_cast<uint32_t*>(&h1);
        oa.z = *reinterpret_cast<uint32_t*>(&h2);
        oa.w = *reinterpret_cast<uint32_t*>(&h3);
        dstA[i] = oa;
        int4 w0 = q[2 * i];
        int4 w1 = q[2 * i + 1];
        __half2 g0 = __floats2half2_rn(s * ((float)w0.x - z), s * ((float)w0.y - z));
        __half2 g1 = __floats2half2_rn(s * ((float)w0.z - z), s * ((float)w0.w - z));
        __half2 g2 = __floats2half2_rn(s * ((float)w1.x - z), s * ((float)w1.y - z));
        __half2 g3 = __floats2half2_rn(s * ((float)w1.z - z), s * ((float)w1.w - z));
        uint4 ob;
        ob.x = *reinterpret_cast<uint32_t*>(&g0);
        ob.y = *reinterpret_cast<uint32_t*>(&g1);
        ob.z = *reinterpret_cast<uint32_t*>(&g2);
        ob.w = *reinterpret_cast<uint32_t*>(&g3);
        dstB[i] = ob;
    }
}

// ---------------- persistent GEMM kernel ----------------
__global__ void __launch_bounds__(256, 1)
gemm_hmma_kernel(const __grid_constant__ CUtensorMap tmA,
                 const __grid_constant__ CUtensorMap tmB,
                 const float* __restrict__ bias,
                 float* __restrict__ out) {
    extern __shared__ char smraw[];
    const uint32_t sb = (smem_u32(smraw) + 1023u) & ~1023u;
    const uint32_t data = sb + SMEM_HDR;

    const int tid = threadIdx.x;
    const int wid = tid >> 5;
    const int lane = tid & 31;
    const int warp_m = wid & 1;       // 2 warps over M (64 rows)
    const int warp_n = wid >> 1;      // 4 warps over N (64 cols)
    const int hsw = wid >> 2;         // warps 4-7 traverse sub-blocks in reverse

    const int bid = blockIdx.x;
    const int G = gridDim.x;
    const int ntiles_cta = (NTILES - 1 - bid) / G + 1;
    const int GI = ntiles_cta * NKITER;

    if (tid == 0) {
        #pragma unroll
        for (int s = 0; s < STAGES; ++s) {
            mbar_init(sb + FULL_OFF(s), 1);
            mbar_init(sb + EMPTY_OFF(s), 8);   // one arrive per warp
        }
    }
    __syncthreads();

    // prologue: fill both stages (tile 0, big-k = 0..1)
    if (tid == 0) {
        int m0p, n0p;
        tile_coords(bid, m0p, n0p);
        #pragma unroll
        for (int s = 0; s < STAGES; ++s) {
            uint32_t st = data + s * STAGE_BYTES;
            mbar_expect_tx(sb + FULL_OFF(s), STAGE_BYTES);
            tma_load_2d(st,                     &tmA, s * 128,      m0p, sb + FULL_OFF(s));
            tma_load_2d(st + A_SUB,             &tmA, s * 128 + 64, m0p, sb + FULL_OFF(s));
            tma_load_2d(st + A_PART,            &tmB, s * 128,      n0p, sb + FULL_OFF(s));
            tma_load_2d(st + A_PART + B_SUB,    &tmB, s * 128 + 64, n0p, sb + FULL_OFF(s));
        }
    }

    // per-thread ldmatrix offsets (relative to sub-block base)
    const int row16 = lane & 15;
    const uint32_t chalf = (lane >> 4) & 1;
    uint32_t a_off[4], b_off[4], a_xor[4], b_xor[4];
    #pragma unroll
    for (int t = 0; t < 4; ++t) {
        int ar = warp_m * 64 + t * 16 + row16;
        a_off[t] = (uint32_t)ar * 128u;
        a_xor[t] = (uint32_t)(ar & 7);
        int br = warp_n * 64 + t * 16 + row16;
        b_off[t] = (uint32_t)br * 128u;
        b_xor[t] = (uint32_t)(br & 7);
    }

    const int lm = lane >> 2;
    const int lc = (lane & 3) * 2;

    for (int tseq = 0; tseq < ntiles_cta; ++tseq) {
        const int tile_id = bid + tseq * G;
        int m0, n0;
        tile_coords(tile_id, m0, n0);

        float acc[4][8][4];
        #pragma unroll
        for (int mt = 0; mt < 4; ++mt)
            #pragma unroll
            for (int nt = 0; nt < 8; ++nt)
                #pragma unroll
                for (int i = 0; i < 4; ++i) acc[mt][nt][i] = 0.0f;

        for (int k = 0; k < NKITER; ++k) {
            const int gi = tseq * NKITER + k;
            const int s = gi & 1;
            const uint32_t ph = (uint32_t)((gi >> 1) & 1);
            const uint32_t stage = data + s * STAGE_BYTES;

            mbar_wait(sb + FULL_OFF(s), ph);

            // two sub-blocks; warps 4-7 take them in reverse order (h ^ hsw)
            // to decorrelate LDSM->MMA stalls between warps sharing an SMSP.
            #pragma unroll
            for (int h = 0; h < 2; ++h) {
                const uint32_t hh = (uint32_t)(h ^ hsw);
                const uint32_t baseA = stage + hh * A_SUB;
                const uint32_t baseB = stage + A_PART + hh * B_SUB;
                #pragma unroll
                for (int ks = 0; ks < 4; ++ks) {
                    uint32_t a[4][4], b[4][4];
                    const uint32_t chunk = ((uint32_t)ks << 1) | chalf;
                    #pragma unroll
                    for (int mt = 0; mt < 4; ++mt)
                        LDSM4(a[mt], baseA + a_off[mt] + ((chunk ^ a_xor[mt]) << 4));
                    #pragma unroll
                    for (int p = 0; p < 4; ++p)
                        LDSM4(b[p], baseB + b_off[p] + ((chunk ^ b_xor[p]) << 4));
                    #pragma unroll
                    for (int mt = 0; mt < 4; ++mt) {
                        #pragma unroll
                        for (int p = 0; p < 4; ++p) {
                            mma16816(acc[mt][2 * p],     a[mt], b[p][0], b[p][2]);
                            mma16816(acc[mt][2 * p + 1], a[mt], b[p][1], b[p][3]);
                        }
                    }
                }
            }

            if (lane == 0) mbar_arrive(sb + EMPTY_OFF(s));

            // producer: refill this stage with big-iter gi+2 (may cross tiles)
            if (tid == 0 && gi + STAGES < GI) {
                mbar_wait(sb + EMPTY_OFF(s), ph);
                const int gnext = gi + STAGES;
                const int ts2 = gnext >> 5;           // NKITER = 32
                const int k2 = gnext & 31;
                int m0p, n0p;
                tile_coords(bid + ts2 * G, m0p, n0p);
                mbar_expect_tx(sb + FULL_OFF(s), STAGE_BYTES);
                tma_load_2d(stage,                  &tmA, k2 * 128,      m0p, sb + FULL_OFF(s));
                tma_load_2d(stage + A_SUB,          &tmA, k2 * 128 + 64, m0p, sb + FULL_OFF(s));
                tma_load_2d(stage + A_PART,         &tmB, k2 * 128,      n0p, sb + FULL_OFF(s));
                tma_load_2d(stage + A_PART + B_SUB, &tmB, k2 * 128 + 64, n0p, sb + FULL_OFF(s));
            }
        }

        // ---------------- epilogue ----------------
        const int col0 = n0 + warp_n * 64 + lc;
        float2 bv[8];
        #pragma unroll
        for (int nt = 0; nt < 8; ++nt)
            bv[nt] = *reinterpret_cast<const float2*>(bias + col0 + nt * 8);

        #pragma unroll
        for (int mt = 0; mt < 4; ++mt) {
            const int r0 = m0 + warp_m * 64 + mt * 16 + lm;
            float* p0 = out + (size_t)r0 * N_TOTAL + col0;
            float* p1 = p0 + (size_t)8 * N_TOTAL;
            #pragma unroll
            for (int nt = 0; nt < 8; ++nt) {
                float2 v0 = {acc[mt][nt][0] + bv[nt].x, acc[mt][nt][1] + bv[nt].y};
                float2 v1 = {acc[mt][nt][2] + bv[nt].x, acc[mt][nt][3] + bv[nt].y};
                *reinterpret_cast<float2*>(p0 + nt * 8) = v0;
                *reinterpret_cast<float2*>(p1 + nt * 8) = v1;
            }
        }
    }
}

// ---------------- host ----------------
typedef CUresult (*PFN_encodeTiled)(CUtensorMap*, CUtensorMapDataType, cuuint32_t, void*,
                                    const cuuint64_t*, const cuuint64_t*,
                                    const cuuint32_t*, const cuuint32_t*,
                                    CUtensorMapInterleave, CUtensorMapSwizzle,
                                    CUtensorMapL2promotion, CUtensorMapFloatOOBfill);

static PFN_encodeTiled get_encode_fn() {
    void* p = nullptr;
    cudaDriverEntryPointQueryResult qr;
    cudaGetDriverEntryPointByVersion("cuTensorMapEncodeTiled", &p, 12000,
                                     cudaEnableDefault, &qr);
    return (PFN_encodeTiled)p;
}

static void make_tmap(PFN_encodeTiled enc, CUtensorMap* tm, void* base,
                      uint64_t rows, uint32_t box_rows) {
    cuuint64_t dims[2]    = {(cuuint64_t)K_TOTAL, (cuuint64_t)rows};
    cuuint64_t strides[1] = {(cuuint64_t)K_TOTAL * 2};
    cuuint32_t box[2]     = {(cuuint32_t)BKH, (cuuint32_t)box_rows};
    cuuint32_t es[2]      = {1, 1};
    enc(tm, CU_TENSOR_MAP_DATA_TYPE_FLOAT16, 2, base, dims, strides, box, es,
        CU_TENSOR_MAP_INTERLEAVE_NONE, CU_TENSOR_MAP_SWIZZLE_128B,
        CU_TENSOR_MAP_L2_PROMOTION_L2_128B, CU_TENSOR_MAP_FLOAT_OOB_FILL_NONE);
}

extern "C" void kernel_launch(void* const* d_in, const int* in_sizes, int n_in,
                              void* d_out, int out_size) {
    const float* x    = (const float*)d_in[0];
    const int*   qw   = (const int*)d_in[1];
    const float* sc   = (const float*)d_in[2];
    const float* zp   = (const float*)d_in[3];
    const float* bias = (const float*)d_in[4];
    float* out = (float*)d_out;

    void *pa = nullptr, *pb = nullptr;
    cudaGetSymbolAddress(&pa, g_A);
    cudaGetSymbolAddress(&pb, g_B);

    const int n8 = (int)(((size_t)M_TOTAL * K_TOTAL) / 8);
    cvt_fused_kernel<<<2048, 256>>>((const float4*)x, (const int4*)qw,
                                    (uint4*)pa, (uint4*)pb, sc, zp, n8);

    PFN_encodeTiled enc = get_encode_fn();
    CUtensorMap tmA, tmB;
    make_tmap(enc, &tmA, pa, M_TOTAL, BM);
    make_tmap(enc, &tmB, pb, N_TOTAL, BN);

    int sm_count = 148;
    cudaDeviceGetAttribute(&sm_count, cudaDevAttrMultiProcessorCount, 0);
    if (sm_count > NTILES) sm_count = NTILES;

    cudaFuncSetAttribute(gemm_hmma_kernel,
                         cudaFuncAttributeMaxDynamicSharedMemorySize, SMEM_TOTAL);
    gemm_hmma_kernel<<<sm_count, 256, SMEM_TOTAL>>>(tmA, tmB, bias, out);
}

// round 16
// speedup vs baseline: 1.0026x; 1.0010x over previous
#include <cuda_runtime.h>
#include <cuda_fp16.h>
#include <cuda.h>
#include <cstdint>
#include <cstddef>

// Problem dims (fixed)
#define M_TOTAL 16384
#define N_TOTAL 16384
#define K_TOTAL 4096

// Tiling: BM=128, BN=256, BK=128 per stage (two 64-wide sub-blocks)
#define BM 128
#define BN 256
#define BKH 64                        // sub-block K width (128 B rows, SW128)
#define STAGES 2
#define NKITER (K_TOTAL / 128)        // 32 big iterations
#define A_SUB (BM * BKH * 2)          // 16384
#define B_SUB (BN * BKH * 2)          // 32768
#define A_PART (2 * A_SUB)            // 32768
#define STAGE_BYTES (A_PART + 2 * B_SUB)   // 98304
#define SMEM_HDR 1024
#define SMEM_TOTAL (1024 + SMEM_HDR + STAGES * STAGE_BYTES)  // 198656
#define GROUP_M 8
#define NUM_N (N_TOTAL / BN)          // 64
#define NTILES ((M_TOTAL / BM) * NUM_N)  // 8192

#define FULL_OFF(s)  ((s) * 16)
#define EMPTY_OFF(s) ((s) * 16 + 8)

// ---------------- fp16 scratch ----------------
__device__ __align__(1024) __half g_A[(size_t)M_TOTAL * K_TOTAL];  // 128 MB
__device__ __align__(1024) __half g_B[(size_t)N_TOTAL * K_TOTAL];  // 128 MB

// ---------------- device helpers ----------------
__device__ __forceinline__ uint32_t smem_u32(const void* p) {
    uint32_t a;
    asm("{ .reg .u64 t; cvta.to.shared.u64 t, %1; cvt.u32.u64 %0, t; }"
        : "=r"(a) : "l"(p));
    return a;
}

__device__ __forceinline__ void mbar_init(uint32_t mbar, uint32_t count) {
    asm volatile("mbarrier.init.shared.b64 [%0], %1;" :: "r"(mbar), "r"(count) : "memory");
}

__device__ __forceinline__ void mbar_expect_tx(uint32_t mbar, uint32_t bytes) {
    asm volatile("mbarrier.arrive.expect_tx.shared.b64 _, [%0], %1;"
                 :: "r"(mbar), "r"(bytes) : "memory");
}

__device__ __forceinline__ void mbar_arrive(uint32_t mbar) {
    asm volatile("mbarrier.arrive.shared.b64 _, [%0];" :: "r"(mbar) : "memory");
}

__device__ __forceinline__ void mbar_wait(uint32_t mbar, uint32_t parity) {
    asm volatile(
        "{\n\t.reg .pred P;\n\t"
        "LAB_WAIT_%=:\n\t"
        "mbarrier.try_wait.parity.acquire.cta.shared::cta.b64 P, [%0], %1, 0x989680;\n\t"
        "@P bra.uni LAB_DONE_%=;\n\t"
        "bra.uni LAB_WAIT_%=;\n\t"
        "LAB_DONE_%=:\n\t}"
        :: "r"(mbar), "r"(parity) : "memory");
}

__device__ __forceinline__ void tma_load_2d(uint32_t dst, const CUtensorMap* map,
                                            int x, int y, uint32_t mbar) {
    asm volatile(
        "cp.async.bulk.tensor.2d.shared::cta.global.tile.mbarrier::complete_tx::bytes "
        "[%0], [%1, {%2, %3}], [%4];"
        :: "r"(dst), "l"(map), "r"(x), "r"(y), "r"(mbar) : "memory");
}

#define LDSM4(R, ADDR) \
    asm volatile("ldmatrix.sync.aligned.m8n8.x4.shared.b16 {%0,%1,%2,%3}, [%4];" \
                 : "=r"((R)[0]), "=r"((R)[1]), "=r"((R)[2]), "=r"((R)[3]) \
                 : "r"(ADDR))

__device__ __forceinline__ void mma16816(float* c, const uint32_t* a,
                                         uint32_t b0, uint32_t b1) {
    asm volatile(
        "mma.sync.aligned.m16n8k16.row.col.f32.f16.f16.f32 "
        "{%0,%1,%2,%3}, {%4,%5,%6,%7}, {%8,%9}, {%0,%1,%2,%3};"
        : "+f"(c[0]), "+f"(c[1]), "+f"(c[2]), "+f"(c[3])
        : "r"(a[0]), "r"(a[1]), "r"(a[2]), "r"(a[3]), "r"(b0), "r"(b1));
}

// tile id -> (m0, n0) grouped raster
__device__ __forceinline__ void tile_coords(int tile_id, int& m0, int& n0) {
    const int per_group = GROUP_M * NUM_N;
    int g = tile_id / per_group;
    int r = tile_id - g * per_group;
    m0 = (g * GROUP_M + (r % GROUP_M)) * BM;
    n0 = (r / GROUP_M) * BN;
}

// ---------------- fused conversion kernel ----------------
__global__ void cvt_fused_kernel(const float4* __restrict__ x,
                                 const int4* __restrict__ q,
                                 uint4* __restrict__ dstA,
                                 uint4* __restrict__ dstB,
                                 const float* __restrict__ scale_p,
                                 const float* __restrict__ zp_p, int n8) {
    const float s = __ldg(scale_p);
    const float z = __ldg(zp_p);
    int i = blockIdx.x * blockDim.x + threadIdx.x;
    int stride = gridDim.x * blockDim.x;
    for (; i < n8; i += stride) {
        float4 v0 = x[2 * i];
        float4 v1 = x[2 * i + 1];
        __half2 h0 = __floats2half2_rn(v0.x, v0.y);
        __half2 h1 = __floats2half2_rn(v0.z, v0.w);
        __half2 h2 = __floats2half2_rn(v1.x, v1.y);
        __half2 h3 = __floats2half2_rn(v1.z, v1.w);
        uint4 oa;
        oa.x = *reinterpret_cast<uint32_t*>(&h0);
        oa.y = *reinterpret_cast<uint32_t*>(&h1);
        oa.z = *reinterpret_cast<uint32_t*>(&h2);
        oa.w = *reinterpret_cast<uint32_t*>(&h3);
        dstA[i] = oa;
        int4 w0 = q[2 * i];
        int4 w1 = q[2 * i + 1];
        __half2 g0 = __floats2half2_rn(s * ((float)w0.x - z), s * ((float)w0.y - z));
        __half2 g1 = __floats2half2_rn(s * ((float)w0.z - z), s * ((float)w0.w - z));
        __half2 g2 = __floats2half2_rn(s * ((float)w1.x - z), s * ((float)w1.y - z));
        __half2 g3 = __floats2half2_rn(s * ((float)w1.z - z), s * ((float)w1.w - z));
        uint4 ob;
        ob.x = *reinterpret_cast<uint32_t*>(&g0);
        ob.y = *reinterpret_cast<uint32_t*>(&g1);
        ob.z = *reinterpret_cast<uint32_t*>(&g2);
        ob.w = *reinterpret_cast<uint32_t*>(&g3);
        dstB[i] = ob;
    }
}

// ---------------- persistent GEMM kernel ----------------
__global__ void __launch_bounds__(256, 1)
gemm_hmma_kernel(const __grid_constant__ CUtensorMap tmA,
                 const __grid_constant__ CUtensorMap tmB,
                 const float* __restrict__ bias,
                 float* __restrict__ out) {
    extern __shared__ char smraw[];
    const uint32_t sb = (smem_u32(smraw) + 1023u) & ~1023u;
    const uint32_t data = sb + SMEM_HDR;

    const int tid = threadIdx.x;
    const int wid = tid >> 5;
    const int lane = tid & 31;
    const int warp_m = wid & 1;       // 2 warps over M (64 rows)
    const int warp_n = wid >> 1;      // 4 warps over N (64 cols)
    const int hsw = wid >> 2;         // warps 4-7 traverse sub-blocks in reverse

    const int bid = blockIdx.x;
    const int G = gridDim.x;
    const int ntiles_cta = (NTILES - 1 - bid) / G + 1;
    const int GI = ntiles_cta * NKITER;

    if (tid == 0) {
        #pragma unroll
        for (int s = 0; s < STAGES; ++s) {
            mbar_init(sb + FULL_OFF(s), 1);
            mbar_init(sb + EMPTY_OFF(s), 8);   // one arrive per warp
        }
    }
    __syncthreads();

    // prologue: fill both stages (tile 0, big-k = 0..1)
    if (tid == 0) {
        int m0p, n0p;
        tile_coords(bid, m0p, n0p);
        #pragma unroll
        for (int s = 0; s < STAGES; ++s) {
            uint32_t st = data + s * STAGE_BYTES;
            mbar_expect_tx(sb + FULL_OFF(s), STAGE_BYTES);
            tma_load_2d(st,                     &tmA, s * 128,      m0p, sb + FULL_OFF(s));
            tma_load_2d(st + A_SUB,             &tmA, s * 128 + 64, m0p, sb + FULL_OFF(s));
            tma_load_2d(st + A_PART,            &tmB, s * 128,      n0p, sb + FULL_OFF(s));
            tma_load_2d(st + A_PART + B_SUB,    &tmB, s * 128 + 64, n0p, sb + FULL_OFF(s));
        }
    }

    // per-thread ldmatrix offsets (relative to sub-block base)
    const int row16 = lane & 15;
    const uint32_t chalf = (lane >> 4) & 1;
    uint32_t a_off[4], b_off[4], a_xor[4], b_xor[4];
    #pragma unroll
    for (int t = 0; t < 4; ++t) {
        int ar = warp_m * 64 + t * 16 + row16;
        a_off[t] = (uint32_t)ar * 128u;
        a_xor[t] = (uint32_t)(ar & 7);
        int br = warp_n * 64 + t * 16 + row16;
        b_off[t] = (uint32_t)br * 128u;
        b_xor[t] = (uint32_t)(br & 7);
    }

    const int lm = lane >> 2;
    const int lc = (lane & 3) * 2;

    for (int tseq = 0; tseq < ntiles_cta; ++tseq) {
        const int tile_id = bid + tseq * G;
        int m0, n0;
        tile_coords(tile_id, m0, n0);

        float acc[4][8][4];
        #pragma unroll
        for (int mt = 0; mt < 4; ++mt)
            #pragma unroll
            for (int nt = 0; nt < 8; ++nt)
                #pragma unroll
                for (int i = 0; i < 4; ++i) acc[mt][nt][i] = 0.0f;

        for (int k = 0; k < NKITER; ++k) {
            const int gi = tseq * NKITER + k;
            const int s = gi & 1;
            const uint32_t ph = (uint32_t)((gi >> 1) & 1);
            const uint32_t stage = data + s * STAGE_BYTES;

            mbar_wait(sb + FULL_OFF(s), ph);

            // two sub-blocks; warps 4-7 take them in reverse order (h ^ hsw)
            // to decorrelate LDSM->MMA stalls between warps sharing an SMSP.
            #pragma unroll
            for (int h = 0; h < 2; ++h) {
                const uint32_t hh = (uint32_t)(h ^ hsw);
                const uint32_t baseA = stage + hh * A_SUB;
                const uint32_t baseB = stage + A_PART + hh * B_SUB;
                #pragma unroll
                for (int ks = 0; ks < 4; ++ks) {
                    uint32_t a[4][4], b[4][4];
                    const uint32_t chunk = ((uint32_t)ks << 1) | chalf;
                    #pragma unroll
                    for (int mt = 0; mt < 4; ++mt)
                        LDSM4(a[mt], baseA + a_off[mt] + ((chunk ^ a_xor[mt]) << 4));
                    #pragma unroll
                    for (int p = 0; p < 4; ++p)
                        LDSM4(b[p], baseB + b_off[p] + ((chunk ^ b_xor[p]) << 4));
                    #pragma unroll
                    for (int mt = 0; mt < 4; ++mt) {
                        #pragma unroll
                        for (int p = 0; p < 4; ++p) {
                            mma16816(acc[mt][2 * p],     a[mt], b[p][0], b[p][2]);
                            mma16816(acc[mt][2 * p + 1], a[mt], b[p][1], b[p][3]);
                        }
                    }
                }
            }

            if (lane == 0) mbar_arrive(sb + EMPTY_OFF(s));

            // producer: refill this stage with big-iter gi+2 (may cross tiles)
            if (tid == 0 && gi + STAGES < GI) {
                mbar_wait(sb + EMPTY_OFF(s), ph);
                const int gnext = gi + STAGES;
                const int ts2 = gnext >> 5;           // NKITER = 32
                const int k2 = gnext & 31;
                int m0p, n0p;
                tile_coords(bid + ts2 * G, m0p, n0p);
                mbar_expect_tx(sb + FULL_OFF(s), STAGE_BYTES);
                tma_load_2d(stage,                  &tmA, k2 * 128,      m0p, sb + FULL_OFF(s));
                tma_load_2d(stage + A_SUB,          &tmA, k2 * 128 + 64, m0p, sb + FULL_OFF(s));
                tma_load_2d(stage + A_PART,         &tmB, k2 * 128,      n0p, sb + FULL_OFF(s));
                tma_load_2d(stage + A_PART + B_SUB, &tmB, k2 * 128 + 64, n0p, sb + FULL_OFF(s));
            }
        }

        // ---------------- epilogue ----------------
        const int col0 = n0 + warp_n * 64 + lc;
        float2 bv[8];
        #pragma unroll
        for (int nt = 0; nt < 8; ++nt)
            bv[nt] = *reinterpret_cast<const float2*>(bias + col0 + nt * 8);

        #pragma unroll
        for (int mt = 0; mt < 4; ++mt) {
            const int r0 = m0 + warp_m * 64 + mt * 16 + lm;
            float* p0 = out + (size_t)r0 * N_TOTAL + col0;
            float* p1 = p0 + (size_t)8 * N_TOTAL;
            #pragma unroll
            for (int nt = 0; nt < 8; ++nt) {
                float2 v0 = {acc[mt][nt][0] + bv[nt].x, acc[mt][nt][1] + bv[nt].y};
                float2 v1 = {acc[mt][nt][2] + bv[nt].x, acc[mt][nt][3] + bv[nt].y};
                *reinterpret_cast<float2*>(p0 + nt * 8) = v0;
                *reinterpret_cast<float2*>(p1 + nt * 8) = v1;
            }
        }
    }
}

// ---------------- host ----------------
typedef CUresult (*PFN_encodeTiled)(CUtensorMap*, CUtensorMapDataType, cuuint32_t, void*,
                                    const cuuint64_t*, const cuuint64_t*,
                                    const cuuint32_t*, const cuuint32_t*,
                                    CUtensorMapInterleave, CUtensorMapSwizzle,
                                    CUtensorMapL2promotion, CUtensorMapFloatOOBfill);

static PFN_encodeTiled get_encode_fn() {
    void* p = nullptr;
    cudaDriverEntryPointQueryResult qr;
    cudaGetDriverEntryPointByVersion("cuTensorMapEncodeTiled", &p, 12000,
                                     cudaEnableDefault, &qr);
    return (PFN_encodeTiled)p;
}

static void make_tmap(PFN_encodeTiled enc, CUtensorMap* tm, void* base,
                      uint64_t rows, uint32_t box_rows) {
    cuuint64_t dims[2]    = {(cuuint64_t)K_TOTAL, (cuuint64_t)rows};
    cuuint64_t strides[1] = {(cuuint64_t)K_TOTAL * 2};
    cuuint32_t box[2]     = {(cuuint32_t)BKH, (cuuint32_t)box_rows};
    cuuint32_t es[2]      = {1, 1};
    enc(tm, CU_TENSOR_MAP_DATA_TYPE_FLOAT16, 2, base, dims, strides, box, es,
        CU_TENSOR_MAP_INTERLEAVE_NONE, CU_TENSOR_MAP_SWIZZLE_128B,
        CU_TENSOR_MAP_L2_PROMOTION_L2_128B, CU_TENSOR_MAP_FLOAT_OOB_FILL_NONE);
}

extern "C" void kernel_launch(void* const* d_in, const int* in_sizes, int n_in,
                              void* d_out, int out_size) {
    const float* x    = (const float*)d_in[0];
    const int*   qw   = (const int*)d_in[1];
    const float* sc   = (const float*)d_in[2];
    const float* zp   = (const float*)d_in[3];
    const float* bias = (const float*)d_in[4];
    float* out = (float*)d_out;

    void *pa = nullptr, *pb = nullptr;
    cudaGetSymbolAddress(&pa, g_A);
    cudaGetSymbolAddress(&pb, g_B);

    const int n8 = (int)(((size_t)M_TOTAL * K_TOTAL) / 8);
    cvt_fused_kernel<<<2048, 256>>>((const float4*)x, (const int4*)qw,
                                    (uint4*)pa, (uint4*)pb, sc, zp, n8);

    PFN_encodeTiled enc = get_encode_fn();
    CUtensorMap tmA, tmB;
    make_tmap(enc, &tmA, pa, M_TOTAL, BM);
    make_tmap(enc, &tmB, pb, N_TOTAL, BN);

    int sm_count = 148;
    cudaDeviceGetAttribute(&sm_count, cudaDevAttrMultiProcessorCount, 0);
    if (sm_count > NTILES) sm_count = NTILES;

    cudaFuncSetAttribute(gemm_hmma_kernel,
                         cudaFuncAttributeMaxDynamicSharedMemorySize, SMEM_TOTAL);
    gemm_hmma_kernel<<<sm_count, 256, SMEM_TOTAL>>>(tmA, tmB, bias, out);
}